// round 1
// baseline (speedup 1.0000x reference)
#include <cuda_runtime.h>

#define W_  640
#define H_  480
#define HW  307200
#define CS  12
#define CI  16
#define CT  28

// ---------------- scratch (device globals, no allocation) ----------------
__device__ float g_w[25 * HW];     // normalized bilateral weights, plane per offset
__device__ float g_qa[CT * HW];    // q double buffer A (sem 0..11, ins 12..27)
__device__ float g_qb[CT * HW];    // q double buffer B
__device__ float g_tA[CT * HW];    // blur horizontal intermediate
__device__ float g_blur[CT * HW];  // blur output

// 13-tap Gaussian, sigma=3, normalized (matches reference float32 to ~1e-7)
__constant__ float c_gk[13] = {
    0.01854402f, 0.03416694f, 0.05633177f, 0.08310854f, 0.10971929f,
    0.12961803f, 0.13702286f, 0.12961803f, 0.10971929f, 0.08310854f,
    0.05633177f, 0.03416694f, 0.01854402f};

// ---------------- init: bilateral weights + initial softmax ----------------
__global__ void __launch_bounds__(256) kInit(const float* __restrict__ img,
                                             const float* __restrict__ slog,
                                             const float* __restrict__ ilog)
{
    int p = blockIdx.x * 256 + threadIdx.x;
    int x = p % W_, y = p / W_;

    float r0 = img[p], g0 = img[HW + p], b0 = img[2 * HW + p];
    float w25[25];
    float den = 0.f;
    #pragma unroll
    for (int o = 0; o < 25; o++) {
        int dy = o / 5 - 2, dx = o % 5 - 2;
        int ny = min(max(y + dy, 0), H_ - 1);
        int nx = min(max(x + dx, 0), W_ - 1);
        int np = ny * W_ + nx;
        float dr = r0 - img[np];
        float dg = g0 - img[HW + np];
        float db = b0 - img[2 * HW + np];
        float cd = dr * dr + dg * dg + db * db;
        float sd = (float)(dy * dy + dx * dx);
        float w = __expf(-sd * 0.05555555556f - cd * 22.22222222f);
        w25[o] = w;
        den += w;
    }
    float inv = 1.0f / den;
    #pragma unroll
    for (int o = 0; o < 25; o++) g_w[o * HW + p] = w25[o] * inv;

    // softmax of semantic logits -> planes 0..11
    {
        float t[CS];
        float m = -1e30f;
        #pragma unroll
        for (int c = 0; c < CS; c++) { t[c] = slog[c * HW + p]; m = fmaxf(m, t[c]); }
        float s = 0.f;
        #pragma unroll
        for (int c = 0; c < CS; c++) { t[c] = __expf(t[c] - m); s += t[c]; }
        float is = 1.0f / s;
        #pragma unroll
        for (int c = 0; c < CS; c++) g_qa[c * HW + p] = t[c] * is;
    }
    // softmax of instance logits -> planes 12..27
    {
        float t[CI];
        float m = -1e30f;
        #pragma unroll
        for (int c = 0; c < CI; c++) { t[c] = ilog[c * HW + p]; m = fmaxf(m, t[c]); }
        float s = 0.f;
        #pragma unroll
        for (int c = 0; c < CI; c++) { t[c] = __expf(t[c] - m); s += t[c]; }
        float is = 1.0f / s;
        #pragma unroll
        for (int c = 0; c < CI; c++) g_qa[(CS + c) * HW + p] = t[c] * is;
    }
}

// ---------------- separable blur, horizontal (zero padding) ----------------
__global__ void __launch_bounds__(256) kBlurH(int src)
{
    const float* in = src ? g_qb : g_qa;
    int p = blockIdx.x * 256 + threadIdx.x;
    int c = blockIdx.y;
    int x = p % W_;
    const float* row = in + c * HW + (p - x);
    float acc = 0.f;
    #pragma unroll
    for (int j = 0; j < 13; j++) {
        int xx = x + j - 6;
        if (xx >= 0 && xx < W_) acc = fmaf(c_gk[j], __ldg(row + xx), acc);
    }
    g_tA[c * HW + p] = acc;
}

// ---------------- separable blur, vertical (zero padding) ----------------
__global__ void __launch_bounds__(256) kBlurV()
{
    int p = blockIdx.x * 256 + threadIdx.x;
    int c = blockIdx.y;
    int x = p % W_, y = p / W_;
    const float* plane = g_tA + c * HW;
    float acc = 0.f;
    #pragma unroll
    for (int j = 0; j < 13; j++) {
        int yy = y + j - 6;
        if (yy >= 0 && yy < H_) acc = fmaf(c_gk[j], __ldg(plane + yy * W_ + x), acc);
    }
    g_blur[c * HW + p] = acc;
}

// ---------------- fused: bilateral + compat + cross + softmaxes ----------------
__global__ void __launch_bounds__(256) kFused(
    int src, float* __restrict__ dout,   // dout != nullptr => write final output there
    const float* __restrict__ slog, const float* __restrict__ ilog,
    const int*   __restrict__ labels,
    const float* __restrict__ ssw_g, const float* __restrict__ sbw_g,
    const float* __restrict__ compat_g,
    const float* __restrict__ isw_g, const float* __restrict__ ibw_g,
    const float* __restrict__ cis_g, const float* __restrict__ csi_g)
{
    const float* q  = src ? g_qb : g_qa;
    float* qn = dout ? dout : (src ? g_qa : g_qb);

    __shared__ float s_compat[CS * CS];
    __shared__ float s_mis[CI * CS];
    __shared__ float s_csi[CI * CS];
    __shared__ float s_sw[CI], s_bw[CI], s_ssw[CS], s_sbw[CS];

    int tid = threadIdx.x;
    if (tid < CS * CS) s_compat[tid] = compat_g[tid];
    if (tid < CI) {
        int l = labels[tid];
        s_sw[tid] = isw_g[l];
        s_bw[tid] = ibw_g[l];
        for (int o = 0; o < CS; o++) {
            s_mis[tid * CS + o] = cis_g[l * CS + o];
            s_csi[tid * CS + o] = csi_g[l * CS + o];
        }
    }
    if (tid < CS) { s_ssw[tid] = ssw_g[tid]; s_sbw[tid] = sbw_g[tid]; }
    __syncthreads();

    int p = blockIdx.x * 256 + tid;
    int x = p % W_, y = p / W_;

    // ---- bilateral: 25-offset weighted gather over all 28 channels ----
    float bil[CT];
    #pragma unroll
    for (int c = 0; c < CT; c++) bil[c] = 0.f;

    for (int o = 0; o < 25; o++) {
        int dy = o / 5 - 2, dx = o % 5 - 2;
        int ny = min(max(y + dy, 0), H_ - 1);
        int nx = min(max(x + dx, 0), W_ - 1);
        int np = ny * W_ + nx;
        float w = g_w[o * HW + p];
        const float* qp = q + np;
        #pragma unroll
        for (int c = 0; c < CT; c++) bil[c] = fmaf(w, __ldg(qp + c * HW), bil[c]);
    }

    // ---- semantic pairwise contributions + compat ----
    float contrib[CS];
    #pragma unroll
    for (int s = 0; s < CS; s++) {
        float bl = g_blur[s * HW + p];
        contrib[s] = s_ssw[s] * bl + s_sbw[s] * bil[s];
    }
    float tmp_sem[CS];
    #pragma unroll
    for (int o2 = 0; o2 < CS; o2++) {
        float acc = slog[o2 * HW + p];
        #pragma unroll
        for (int i = 0; i < CS; i++) acc = fmaf(s_compat[i * CS + o2], contrib[i], acc);
        tmp_sem[o2] = acc;
    }

    // ---- instance pairwise contributions ----
    float tmp_ins[CI];
    #pragma unroll
    for (int j = 0; j < CI; j++) {
        float bl = g_blur[(CS + j) * HW + p];
        tmp_ins[j] = ilog[j * HW + p] + s_sw[j] * bl + s_bw[j] * bil[CS + j];
    }

    // ---- softmax(tmp_ins), softmax(tmp_sem) ----
    float e_ins[CI];
    {
        float m = -1e30f;
        #pragma unroll
        for (int j = 0; j < CI; j++) m = fmaxf(m, tmp_ins[j]);
        float s = 0.f;
        #pragma unroll
        for (int j = 0; j < CI; j++) { e_ins[j] = __expf(tmp_ins[j] - m); s += e_ins[j]; }
        float is = 1.0f / s;
        #pragma unroll
        for (int j = 0; j < CI; j++) e_ins[j] *= is;
    }
    float e_sem[CS];
    {
        float m = -1e30f;
        #pragma unroll
        for (int i = 0; i < CS; i++) m = fmaxf(m, tmp_sem[i]);
        float s = 0.f;
        #pragma unroll
        for (int i = 0; i < CS; i++) { e_sem[i] = __expf(tmp_sem[i] - m); s += e_sem[i]; }
        float is = 1.0f / s;
        #pragma unroll
        for (int i = 0; i < CS; i++) e_sem[i] *= is;
    }

    // ---- cross updates ----
    float sem_new[CS];
    #pragma unroll
    for (int o2 = 0; o2 < CS; o2++) {
        float acc = tmp_sem[o2];
        #pragma unroll
        for (int j = 0; j < CI; j++) acc = fmaf(s_mis[j * CS + o2], e_ins[j], acc);
        sem_new[o2] = acc;
    }
    float ins_new[CI];
    #pragma unroll
    for (int j = 0; j < CI; j++) {
        float acc = tmp_ins[j];
        #pragma unroll
        for (int s2 = 0; s2 < CS; s2++) acc = fmaf(s_csi[j * CS + s2], e_sem[s2], acc);
        ins_new[j] = acc;
    }

    // ---- final softmaxes -> write q ----
    {
        float m = -1e30f;
        #pragma unroll
        for (int i = 0; i < CS; i++) m = fmaxf(m, sem_new[i]);
        float s = 0.f;
        float e[CS];
        #pragma unroll
        for (int i = 0; i < CS; i++) { e[i] = __expf(sem_new[i] - m); s += e[i]; }
        float is = 1.0f / s;
        #pragma unroll
        for (int i = 0; i < CS; i++) qn[i * HW + p] = e[i] * is;
    }
    {
        float m = -1e30f;
        #pragma unroll
        for (int j = 0; j < CI; j++) m = fmaxf(m, ins_new[j]);
        float s = 0.f;
        float e[CI];
        #pragma unroll
        for (int j = 0; j < CI; j++) { e[j] = __expf(ins_new[j] - m); s += e[j]; }
        float is = 1.0f / s;
        #pragma unroll
        for (int j = 0; j < CI; j++) qn[(CS + j) * HW + p] = e[j] * is;
    }
}

// ---------------- launch ----------------
extern "C" void kernel_launch(void* const* d_in, const int* in_sizes, int n_in,
                              void* d_out, int out_size)
{
    const float* img    = (const float*)d_in[0];
    const float* slog   = (const float*)d_in[1];
    const float* ilog   = (const float*)d_in[2];
    const int*   labels = (const int*)  d_in[3];
    const float* ssw    = (const float*)d_in[4];
    const float* sbw    = (const float*)d_in[5];
    const float* compat = (const float*)d_in[6];
    const float* isw    = (const float*)d_in[7];
    const float* ibw    = (const float*)d_in[8];
    const float* cis    = (const float*)d_in[9];
    const float* csi    = (const float*)d_in[10];
    float* out = (float*)d_out;

    const int NB = HW / 256;  // 1200, exact
    dim3 blk(256);
    dim3 grdC(NB, CT);

    kInit<<<NB, blk>>>(img, slog, ilog);

    // iter 0: q in A, write B
    kBlurH<<<grdC, blk>>>(0);
    kBlurV<<<grdC, blk>>>();
    kFused<<<NB, blk>>>(0, nullptr, slog, ilog, labels, ssw, sbw, compat, isw, ibw, cis, csi);
    // iter 1: q in B, write A
    kBlurH<<<grdC, blk>>>(1);
    kBlurV<<<grdC, blk>>>();
    kFused<<<NB, blk>>>(1, nullptr, slog, ilog, labels, ssw, sbw, compat, isw, ibw, cis, csi);
    // iter 2: q in A, write final output
    kBlurH<<<grdC, blk>>>(0);
    kBlurV<<<grdC, blk>>>();
    kFused<<<NB, blk>>>(0, out, slog, ilog, labels, ssw, sbw, compat, isw, ibw, cis, csi);
}

// round 2
// speedup vs baseline: 2.1211x; 2.1211x over previous
#include <cuda_runtime.h>

#define W_  640
#define H_  480
#define HW  307200
#define CS  12
#define CI  16
#define CT  28

// ---------------- scratch (device globals, no allocation) ----------------
__device__ float g_w[25 * HW];     // normalized bilateral weights, plane per offset
__device__ float g_qa[CT * HW];    // q double buffer A (sem 0..11, ins 12..27)
__device__ float g_qb[CT * HW];    // q double buffer B
__device__ float g_blur[CT * HW];  // blur output

// 13-tap Gaussian, sigma=3, normalized
__constant__ float c_gk[13] = {
    0.01854402f, 0.03416694f, 0.05633177f, 0.08310854f, 0.10971929f,
    0.12961803f, 0.13702286f, 0.12961803f, 0.10971929f, 0.08310854f,
    0.05633177f, 0.03416694f, 0.01854402f};

// ---------------- init: bilateral weights + initial softmax ----------------
__global__ void __launch_bounds__(256) kInit(const float* __restrict__ img,
                                             const float* __restrict__ slog,
                                             const float* __restrict__ ilog)
{
    int p = blockIdx.x * 256 + threadIdx.x;
    int x = p % W_, y = p / W_;

    float r0 = img[p], g0 = img[HW + p], b0 = img[2 * HW + p];
    float w25[25];
    float den = 0.f;
    #pragma unroll
    for (int o = 0; o < 25; o++) {
        int dy = o / 5 - 2, dx = o % 5 - 2;
        int ny = min(max(y + dy, 0), H_ - 1);
        int nx = min(max(x + dx, 0), W_ - 1);
        int np = ny * W_ + nx;
        float dr = r0 - __ldg(img + np);
        float dg = g0 - __ldg(img + HW + np);
        float db = b0 - __ldg(img + 2 * HW + np);
        float cd = dr * dr + dg * dg + db * db;
        float sd = (float)(dy * dy + dx * dx);
        float w = __expf(-sd * 0.05555555556f - cd * 22.22222222f);
        w25[o] = w;
        den += w;
    }
    float inv = 1.0f / den;
    #pragma unroll
    for (int o = 0; o < 25; o++) g_w[o * HW + p] = w25[o] * inv;

    {
        float t[CS];
        float m = -1e30f;
        #pragma unroll
        for (int c = 0; c < CS; c++) { t[c] = slog[c * HW + p]; m = fmaxf(m, t[c]); }
        float s = 0.f;
        #pragma unroll
        for (int c = 0; c < CS; c++) { t[c] = __expf(t[c] - m); s += t[c]; }
        float is = 1.0f / s;
        #pragma unroll
        for (int c = 0; c < CS; c++) g_qa[c * HW + p] = t[c] * is;
    }
    {
        float t[CI];
        float m = -1e30f;
        #pragma unroll
        for (int c = 0; c < CI; c++) { t[c] = ilog[c * HW + p]; m = fmaxf(m, t[c]); }
        float s = 0.f;
        #pragma unroll
        for (int c = 0; c < CI; c++) { t[c] = __expf(t[c] - m); s += t[c]; }
        float is = 1.0f / s;
        #pragma unroll
        for (int c = 0; c < CI; c++) g_qa[(CS + c) * HW + p] = t[c] * is;
    }
}

// ---------------- fused separable blur (H then V), zero padding ----------------
// Tile: 64 x 16 output px per block-channel. H-blur into smem for 28 rows
// (16 + 2*6 halo), then V-blur from smem.
#define BTX 64
#define BTY 16
#define HR  (BTY + 12)

__global__ void __launch_bounds__(256) kBlur(int src)
{
    const float* q = src ? g_qb : g_qa;
    __shared__ float sH[HR][BTX];

    int c  = blockIdx.z;
    int x0 = blockIdx.x * BTX;
    int y0 = blockIdx.y * BTY;
    const float* plane = q + c * HW;
    int tid = threadIdx.x;

    // Stage 1: horizontal blur, HR*16 float4-tasks
    for (int t = tid; t < HR * (BTX / 4); t += 256) {
        int r  = t >> 4;
        int xg = t & 15;
        int gy = y0 + r - 6;
        int x4 = x0 + xg * 4;
        float4 out = make_float4(0.f, 0.f, 0.f, 0.f);
        if (gy >= 0 && gy < H_) {
            const float* row = plane + gy * W_;
            float f[20];
            #pragma unroll
            for (int s = 0; s < 5; s++) {
                int xb = x4 - 8 + s * 4;
                if (xb >= 0 && xb + 3 < W_) {
                    float4 v = __ldg((const float4*)(row + xb));
                    f[s * 4 + 0] = v.x; f[s * 4 + 1] = v.y;
                    f[s * 4 + 2] = v.z; f[s * 4 + 3] = v.w;
                } else {
                    #pragma unroll
                    for (int k = 0; k < 4; k++) {
                        int xx = xb + k;
                        f[s * 4 + k] = (xx >= 0 && xx < W_) ? __ldg(row + xx) : 0.f;
                    }
                }
            }
            #pragma unroll
            for (int j = 0; j < 4; j++) {
                float a = 0.f;
                #pragma unroll
                for (int tt = 0; tt < 13; tt++) a = fmaf(c_gk[tt], f[j + 2 + tt], a);
                ((float*)&out)[j] = a;
            }
        }
        *(float4*)&sH[r][xg * 4] = out;
    }
    __syncthreads();

    // Stage 2: vertical blur, each thread 4 output rows
    int tx = tid & 63, ty = tid >> 6;
    #pragma unroll
    for (int k = 0; k < 4; k++) {
        int ry = ty + k * 4;
        float a = 0.f;
        #pragma unroll
        for (int tt = 0; tt < 13; tt++) a = fmaf(c_gk[tt], sH[ry + tt][tx], a);
        g_blur[c * HW + (y0 + ry) * W_ + x0 + tx] = a;
    }
}

// ---------------- fused: bilateral (smem tile) + compat + cross + softmaxes --
// Tile: 64 x 4 px, halo 2 -> 68 x 8 per channel, all 28 channels in smem.
#define FTX 64
#define FTY 4
#define TCOL 68
#define TROW 8
#define TSZ  (TCOL * TROW)   // 544

__global__ void __launch_bounds__(256) kFused(
    int src, float* __restrict__ dout,
    const float* __restrict__ slog, const float* __restrict__ ilog,
    const int*   __restrict__ labels,
    const float* __restrict__ ssw_g, const float* __restrict__ sbw_g,
    const float* __restrict__ compat_g,
    const float* __restrict__ isw_g, const float* __restrict__ ibw_g,
    const float* __restrict__ cis_g, const float* __restrict__ csi_g)
{
    extern __shared__ float sm[];
    float* sq       = sm;                 // CT * TSZ
    float* s_compat = sq + CT * TSZ;      // 144
    float* s_mis    = s_compat + 144;     // 192
    float* s_csi    = s_mis + 192;        // 192
    float* s_sw     = s_csi + 192;        // 16
    float* s_bw     = s_sw + 16;          // 16
    float* s_ssw    = s_bw + 16;          // 12
    float* s_sbw    = s_ssw + 12;         // 12

    const float* q  = src ? g_qb : g_qa;
    float* qn = dout ? dout : (src ? g_qa : g_qb);

    int tid = threadIdx.x;

    if (tid < CS * CS) s_compat[tid] = compat_g[tid];
    if (tid >= 160 && tid < 160 + CI) {
        int j = tid - 160;
        int l = labels[j];
        s_sw[j] = isw_g[l];
        s_bw[j] = ibw_g[l];
        #pragma unroll
        for (int s = 0; s < CS; s++) {
            s_mis[j * CS + s] = cis_g[l * CS + s];
            s_csi[j * CS + s] = csi_g[l * CS + s];
        }
    }
    if (tid >= 192 && tid < 192 + CS) {
        int s = tid - 192;
        s_ssw[s] = ssw_g[s];
        s_sbw[s] = sbw_g[s];
    }

    int x0 = blockIdx.x * FTX;
    int y0 = blockIdx.y * FTY;

    // fill q tile (clamped halo) for all 28 channels
    for (int idx = tid; idx < TSZ; idx += 256) {
        int r  = idx / TCOL;
        int cc = idx - r * TCOL;
        int gy = min(max(y0 + r - 2, 0), H_ - 1);
        int gx = min(max(x0 + cc - 2, 0), W_ - 1);
        const float* srcp = q + gy * W_ + gx;
        #pragma unroll
        for (int c = 0; c < CT; c++)
            sq[c * TSZ + idx] = __ldg(srcp + c * HW);
    }
    __syncthreads();

    int tx = tid & 63, ty = tid >> 6;
    int p  = (y0 + ty) * W_ + x0 + tx;

    // weights in registers (coalesced loads, high MLP)
    float w[25];
    #pragma unroll
    for (int o = 0; o < 25; o++) w[o] = __ldg(&g_w[o * HW + p]);

    // ---- bilateral from smem ----
    float bil[CT];
    #pragma unroll
    for (int c = 0; c < CT; c++) bil[c] = 0.f;

    #pragma unroll
    for (int o = 0; o < 25; o++) {
        int dy = o / 5, dx = o % 5;          // 0..4 -> tile row ty+dy, col tx+dx
        const float* base = sq + (ty + dy) * TCOL + (tx + dx);
        float ww = w[o];
        #pragma unroll
        for (int c = 0; c < CT; c++)
            bil[c] = fmaf(ww, base[c * TSZ], bil[c]);
    }

    // ---- semantic pairwise + compat ----
    float contrib[CS];
    #pragma unroll
    for (int s = 0; s < CS; s++) {
        float bl = __ldg(&g_blur[s * HW + p]);
        contrib[s] = s_ssw[s] * bl + s_sbw[s] * bil[s];
    }
    float tmp_sem[CS];
    #pragma unroll
    for (int o2 = 0; o2 < CS; o2++) {
        float acc = __ldg(slog + o2 * HW + p);
        #pragma unroll
        for (int i = 0; i < CS; i++) acc = fmaf(s_compat[i * CS + o2], contrib[i], acc);
        tmp_sem[o2] = acc;
    }

    // ---- instance pairwise ----
    float tmp_ins[CI];
    #pragma unroll
    for (int j = 0; j < CI; j++) {
        float bl = __ldg(&g_blur[(CS + j) * HW + p]);
        tmp_ins[j] = __ldg(ilog + j * HW + p) + s_sw[j] * bl + s_bw[j] * bil[CS + j];
    }

    // ---- softmax(tmp_ins), softmax(tmp_sem) ----
    float e_ins[CI];
    {
        float m = -1e30f;
        #pragma unroll
        for (int j = 0; j < CI; j++) m = fmaxf(m, tmp_ins[j]);
        float s = 0.f;
        #pragma unroll
        for (int j = 0; j < CI; j++) { e_ins[j] = __expf(tmp_ins[j] - m); s += e_ins[j]; }
        float is = 1.0f / s;
        #pragma unroll
        for (int j = 0; j < CI; j++) e_ins[j] *= is;
    }
    float e_sem[CS];
    {
        float m = -1e30f;
        #pragma unroll
        for (int i = 0; i < CS; i++) m = fmaxf(m, tmp_sem[i]);
        float s = 0.f;
        #pragma unroll
        for (int i = 0; i < CS; i++) { e_sem[i] = __expf(tmp_sem[i] - m); s += e_sem[i]; }
        float is = 1.0f / s;
        #pragma unroll
        for (int i = 0; i < CS; i++) e_sem[i] *= is;
    }

    // ---- cross updates ----
    float sem_new[CS];
    #pragma unroll
    for (int o2 = 0; o2 < CS; o2++) {
        float acc = tmp_sem[o2];
        #pragma unroll
        for (int j = 0; j < CI; j++) acc = fmaf(s_mis[j * CS + o2], e_ins[j], acc);
        sem_new[o2] = acc;
    }
    float ins_new[CI];
    #pragma unroll
    for (int j = 0; j < CI; j++) {
        float acc = tmp_ins[j];
        #pragma unroll
        for (int s2 = 0; s2 < CS; s2++) acc = fmaf(s_csi[j * CS + s2], e_sem[s2], acc);
        ins_new[j] = acc;
    }

    // ---- final softmaxes -> write q ----
    {
        float m = -1e30f;
        #pragma unroll
        for (int i = 0; i < CS; i++) m = fmaxf(m, sem_new[i]);
        float s = 0.f;
        float e[CS];
        #pragma unroll
        for (int i = 0; i < CS; i++) { e[i] = __expf(sem_new[i] - m); s += e[i]; }
        float is = 1.0f / s;
        #pragma unroll
        for (int i = 0; i < CS; i++) qn[i * HW + p] = e[i] * is;
    }
    {
        float m = -1e30f;
        #pragma unroll
        for (int j = 0; j < CI; j++) m = fmaxf(m, ins_new[j]);
        float s = 0.f;
        float e[CI];
        #pragma unroll
        for (int j = 0; j < CI; j++) { e[j] = __expf(ins_new[j] - m); s += e[j]; }
        float is = 1.0f / s;
        #pragma unroll
        for (int j = 0; j < CI; j++) qn[(CS + j) * HW + p] = e[j] * is;
    }
}

// ---------------- launch ----------------
extern "C" void kernel_launch(void* const* d_in, const int* in_sizes, int n_in,
                              void* d_out, int out_size)
{
    const float* img    = (const float*)d_in[0];
    const float* slog   = (const float*)d_in[1];
    const float* ilog   = (const float*)d_in[2];
    const int*   labels = (const int*)  d_in[3];
    const float* ssw    = (const float*)d_in[4];
    const float* sbw    = (const float*)d_in[5];
    const float* compat = (const float*)d_in[6];
    const float* isw    = (const float*)d_in[7];
    const float* ibw    = (const float*)d_in[8];
    const float* cis    = (const float*)d_in[9];
    const float* csi    = (const float*)d_in[10];
    float* out = (float*)d_out;

    const int FUSED_SMEM = (CT * TSZ + 144 + 192 + 192 + 16 + 16 + 12 + 12) * 4;
    cudaFuncSetAttribute(kFused, cudaFuncAttributeMaxDynamicSharedMemorySize, FUSED_SMEM);

    dim3 blk(256);
    dim3 grdBlur(W_ / BTX, H_ / BTY, CT);     // 10 x 30 x 28
    dim3 grdFused(W_ / FTX, H_ / FTY);        // 10 x 120

    kInit<<<HW / 256, blk>>>(img, slog, ilog);

    // iter 0: q in A, write B
    kBlur<<<grdBlur, blk>>>(0);
    kFused<<<grdFused, blk, FUSED_SMEM>>>(0, nullptr, slog, ilog, labels, ssw, sbw, compat, isw, ibw, cis, csi);
    // iter 1: q in B, write A
    kBlur<<<grdBlur, blk>>>(1);
    kFused<<<grdFused, blk, FUSED_SMEM>>>(1, nullptr, slog, ilog, labels, ssw, sbw, compat, isw, ibw, cis, csi);
    // iter 2: q in A, write final output
    kBlur<<<grdBlur, blk>>>(0);
    kFused<<<grdFused, blk, FUSED_SMEM>>>(0, out, slog, ilog, labels, ssw, sbw, compat, isw, ibw, cis, csi);
}